// round 1
// baseline (speedup 1.0000x reference)
#include <cuda_runtime.h>
#include <math.h>

// Problem constants
#define TOKENS 8192        // b*n = 4*2048
#define DIM    512
#define CODES  8192
#define DECAYF 0.8f
#define OMDF   (1.0f - 0.8f)
#define EPSF   1e-5f

// Output layout (floats), tuple order flattened:
// quantize[4,2048,512], ind[4,2048], dist[4,2048,8192],
// cluster_size[1,8192], embed_avg[1,8192,512], embed[1,8192,512]
#define OFF_Q    ((size_t)0)
#define OFF_IND  ((size_t)4194304)
#define OFF_DIST ((size_t)4202496)
#define OFF_CS   ((size_t)71311360)
#define OFF_EA   ((size_t)71319552)
#define OFF_E    ((size_t)75513856)

// Scratch (device globals; no allocations allowed)
__device__ float g_xn[(size_t)TOKENS * DIM];   // l2-normalized x
__device__ int   g_ind[TOKENS];
__device__ float g_denom;

// ---------------------------------------------------------------------------
// K1: l2-normalize each token row of x into g_xn. One block per row.
// ---------------------------------------------------------------------------
__global__ void k_normalize(const float* __restrict__ x) {
    int t = blockIdx.x;
    const float4* row = (const float4*)(x + (size_t)t * DIM);
    float4 a = row[threadIdx.x];                 // 128 threads * 4 = 512
    float ss = a.x * a.x + a.y * a.y + a.z * a.z + a.w * a.w;
    #pragma unroll
    for (int o = 16; o > 0; o >>= 1) ss += __shfl_xor_sync(0xffffffffu, ss, o);
    __shared__ float warpsum[4];
    __shared__ float s_inv;
    if ((threadIdx.x & 31) == 0) warpsum[threadIdx.x >> 5] = ss;
    __syncthreads();
    if (threadIdx.x == 0) {
        float tot = warpsum[0] + warpsum[1] + warpsum[2] + warpsum[3];
        s_inv = 1.0f / fmaxf(sqrtf(tot), 1e-6f);
    }
    __syncthreads();
    float inv = s_inv;
    float4 o4 = make_float4(a.x * inv, a.y * inv, a.z * inv, a.w * inv);
    ((float4*)(g_xn + (size_t)t * DIM))[threadIdx.x] = o4;
}

// ---------------------------------------------------------------------------
// K2: dist = g_xn @ embed^T   (both K-major; exact fp32)
// 128x128 tile, BK=8, 256 threads, 8x8 per-thread microtile.
// ---------------------------------------------------------------------------
__global__ __launch_bounds__(256, 2) void k_gemm(const float* __restrict__ Bmat,
                                                 float* __restrict__ dist) {
    __shared__ float As[8][128];
    __shared__ float Bs[8][128];

    int tid = threadIdx.x;
    int rowBase = blockIdx.y * 128;
    int colBase = blockIdx.x * 128;

    const float* Aptr = g_xn + (size_t)(rowBase + (tid >> 1)) * DIM + (tid & 1) * 4;
    const float* Bptr = Bmat + (size_t)(colBase + (tid >> 1)) * DIM + (tid & 1) * 4;

    int tr = tid >> 4;   // 0..15: row group
    int tc = tid & 15;   // 0..15: col group

    float acc[8][8];
    #pragma unroll
    for (int i = 0; i < 8; i++)
        #pragma unroll
        for (int j = 0; j < 8; j++) acc[i][j] = 0.0f;

    int r  = tid >> 1;
    int ks = (tid & 1) * 4;

    for (int k0 = 0; k0 < DIM; k0 += 8) {
        float4 av = *(const float4*)(Aptr + k0);
        float4 bv = *(const float4*)(Bptr + k0);
        __syncthreads();   // previous iteration's compute done
        As[ks + 0][r] = av.x; As[ks + 1][r] = av.y;
        As[ks + 2][r] = av.z; As[ks + 3][r] = av.w;
        Bs[ks + 0][r] = bv.x; Bs[ks + 1][r] = bv.y;
        Bs[ks + 2][r] = bv.z; Bs[ks + 3][r] = bv.w;
        __syncthreads();

        #pragma unroll
        for (int kk = 0; kk < 8; kk++) {
            float a[8], b[8];
            #pragma unroll
            for (int i = 0; i < 8; i++) a[i] = As[kk][tr * 8 + i];
            #pragma unroll
            for (int j = 0; j < 8; j++) b[j] = Bs[kk][tc * 8 + j];
            #pragma unroll
            for (int i = 0; i < 8; i++)
                #pragma unroll
                for (int j = 0; j < 8; j++) acc[i][j] += a[i] * b[j];
        }
    }

    #pragma unroll
    for (int i = 0; i < 8; i++) {
        float* o = dist + (size_t)(rowBase + tr * 8 + i) * CODES + colBase + tc * 8;
        ((float4*)o)[0] = make_float4(acc[i][0], acc[i][1], acc[i][2], acc[i][3]);
        ((float4*)o)[1] = make_float4(acc[i][4], acc[i][5], acc[i][6], acc[i][7]);
    }
}

// ---------------------------------------------------------------------------
// K3: row argmax of dist (first-max tie break, matching jnp.argmax).
// ---------------------------------------------------------------------------
__global__ void k_argmax(const float* __restrict__ dist, float* __restrict__ out_ind) {
    int t = blockIdx.x;
    const float4* row = (const float4*)(dist + (size_t)t * CODES);
    float best = -INFINITY;
    int bi = 0;
    for (int c4 = threadIdx.x; c4 < CODES / 4; c4 += 256) {
        float4 v = row[c4];
        int c = c4 * 4;
        if (v.x > best) { best = v.x; bi = c; }
        if (v.y > best) { best = v.y; bi = c + 1; }
        if (v.z > best) { best = v.z; bi = c + 2; }
        if (v.w > best) { best = v.w; bi = c + 3; }
    }
    __shared__ float sv[256];
    __shared__ int   si[256];
    sv[threadIdx.x] = best;
    si[threadIdx.x] = bi;
    __syncthreads();
    for (int s = 128; s > 0; s >>= 1) {
        if (threadIdx.x < s) {
            float ov = sv[threadIdx.x + s];
            int   oi = si[threadIdx.x + s];
            if (ov > sv[threadIdx.x] ||
                (ov == sv[threadIdx.x] && oi < si[threadIdx.x])) {
                sv[threadIdx.x] = ov;
                si[threadIdx.x] = oi;
            }
        }
        __syncthreads();
    }
    if (threadIdx.x == 0) {
        g_ind[t] = si[0];
        out_ind[t] = (float)si[0];
    }
}

// ---------------------------------------------------------------------------
// K4: quantize = embed[ind]  (gather rows)
// ---------------------------------------------------------------------------
__global__ void k_quantize(const float* __restrict__ embed, float* __restrict__ out_q) {
    int t = blockIdx.x;
    int c = g_ind[t];
    float4 v = ((const float4*)(embed + (size_t)c * DIM))[threadIdx.x];
    ((float4*)(out_q + (size_t)t * DIM))[threadIdx.x] = v;
}

// ---------------------------------------------------------------------------
// K5a: init EMA outputs with DECAY * old
// ---------------------------------------------------------------------------
__global__ void k_init_ema(const float* __restrict__ cs, const float* __restrict__ ea,
                           float* __restrict__ out_cs, float* __restrict__ out_ea) {
    size_t total = (size_t)CODES * DIM;
    for (size_t i = blockIdx.x * (size_t)blockDim.x + threadIdx.x; i < total;
         i += (size_t)gridDim.x * blockDim.x) {
        out_ea[i] = DECAYF * ea[i];
        if (i < CODES) out_cs[i] = DECAYF * cs[i];
    }
}

// ---------------------------------------------------------------------------
// K5b: scatter (1-DECAY)*xn into embed_avg[ind], (1-DECAY) into cluster_size[ind]
// ---------------------------------------------------------------------------
__global__ void k_scatter(float* __restrict__ out_cs, float* __restrict__ out_ea) {
    int t = blockIdx.x;
    int c = g_ind[t];
    const float4* xr = (const float4*)(g_xn + (size_t)t * DIM);
    float* er = out_ea + (size_t)c * DIM;
    float4 v = xr[threadIdx.x];
    int d = threadIdx.x * 4;
    atomicAdd(er + d + 0, OMDF * v.x);
    atomicAdd(er + d + 1, OMDF * v.y);
    atomicAdd(er + d + 2, OMDF * v.z);
    atomicAdd(er + d + 3, OMDF * v.w);
    if (threadIdx.x == 0) atomicAdd(out_cs + c, OMDF);
}

// ---------------------------------------------------------------------------
// K6: denom = sum(new_cluster_size)
// ---------------------------------------------------------------------------
__global__ void k_denom(const float* __restrict__ out_cs) {
    float s = 0.0f;
    for (int i = threadIdx.x; i < CODES; i += 1024) s += out_cs[i];
    #pragma unroll
    for (int o = 16; o > 0; o >>= 1) s += __shfl_xor_sync(0xffffffffu, s, o);
    __shared__ float ws[32];
    if ((threadIdx.x & 31) == 0) ws[threadIdx.x >> 5] = s;
    __syncthreads();
    if (threadIdx.x == 0) {
        float tot = 0.0f;
        for (int i = 0; i < 32; i++) tot += ws[i];
        g_denom = tot;
    }
}

// ---------------------------------------------------------------------------
// K7: new_embed = l2norm(new_embed_avg / smoothed)
// ---------------------------------------------------------------------------
__global__ void k_newembed(const float* __restrict__ out_cs,
                           const float* __restrict__ out_ea,
                           float* __restrict__ out_e) {
    int c = blockIdx.x;
    float denom = g_denom;
    float smoothed = (out_cs[c] + EPSF) / (denom + (float)CODES * EPSF) * denom;
    float invs = 1.0f / smoothed;
    float4 v = ((const float4*)(out_ea + (size_t)c * DIM))[threadIdx.x];
    float4 w = make_float4(v.x * invs, v.y * invs, v.z * invs, v.w * invs);
    float ss = w.x * w.x + w.y * w.y + w.z * w.z + w.w * w.w;
    #pragma unroll
    for (int o = 16; o > 0; o >>= 1) ss += __shfl_xor_sync(0xffffffffu, ss, o);
    __shared__ float warpsum[4];
    __shared__ float s_inv;
    if ((threadIdx.x & 31) == 0) warpsum[threadIdx.x >> 5] = ss;
    __syncthreads();
    if (threadIdx.x == 0) {
        float tot = warpsum[0] + warpsum[1] + warpsum[2] + warpsum[3];
        s_inv = 1.0f / fmaxf(sqrtf(tot), 1e-6f);
    }
    __syncthreads();
    float inv = s_inv;
    float4 o4 = make_float4(w.x * inv, w.y * inv, w.z * inv, w.w * inv);
    ((float4*)(out_e + (size_t)c * DIM))[threadIdx.x] = o4;
}

// ---------------------------------------------------------------------------
extern "C" void kernel_launch(void* const* d_in, const int* in_sizes, int n_in,
                              void* d_out, int out_size) {
    const float* x     = (const float*)d_in[0];
    const float* embed = (const float*)d_in[1];
    const float* cs    = (const float*)d_in[2];
    const float* ea    = (const float*)d_in[3];
    float* out = (float*)d_out;

    k_normalize<<<TOKENS, 128>>>(x);
    k_gemm<<<dim3(CODES / 128, TOKENS / 128), 256>>>(embed, out + OFF_DIST);
    k_argmax<<<TOKENS, 256>>>(out + OFF_DIST, out + OFF_IND);
    k_quantize<<<TOKENS, 128>>>(embed, out + OFF_Q);
    k_init_ema<<<2048, 256>>>(cs, ea, out + OFF_CS, out + OFF_EA);
    k_scatter<<<TOKENS, 128>>>(out + OFF_CS, out + OFF_EA);
    k_denom<<<1, 1024>>>(out + OFF_CS);
    k_newembed<<<CODES, 128>>>(out + OFF_CS, out + OFF_EA, out + OFF_E);
}

// round 4
// speedup vs baseline: 2.0613x; 2.0613x over previous
#include <cuda_runtime.h>
#include <cuda_bf16.h>
#include <cstdint>
#include <math.h>

// Problem constants
#define TOKENS 8192        // b*n = 4*2048
#define DIM    512
#define KPRIME 1536        // 3 * DIM (hi*hi + hi*lo + lo*hi split-K)
#define CODES  8192
#define DECAYF 0.8f
#define OMDF   (1.0f - 0.8f)
#define EPSF   1e-5f

// Output layout (floats), tuple order flattened
#define OFF_Q    ((size_t)0)
#define OFF_IND  ((size_t)4194304)
#define OFF_DIST ((size_t)4202496)
#define OFF_CS   ((size_t)71311360)
#define OFF_EA   ((size_t)71319552)
#define OFF_E    ((size_t)75513856)

// Scratch (device globals; no allocations allowed)
__device__ float g_xn[(size_t)TOKENS * DIM];   // l2-normalized x
__device__ int   g_ind[TOKENS];
__device__ float g_denom;
__device__ __nv_bfloat16 g_A[(size_t)TOKENS * KPRIME];  // [hi | hi | lo]
__device__ __nv_bfloat16 g_B[(size_t)CODES  * KPRIME];  // [hi | lo | hi]

// ---------------------------------------------------------------------------
// helpers
// ---------------------------------------------------------------------------
__device__ __forceinline__ uint32_t smem_u32(const void* p) {
    uint32_t a;
    asm("{ .reg .u64 t; cvta.to.shared.u64 t, %1; cvt.u32.u64 %0, t; }" : "=r"(a) : "l"(p));
    return a;
}
__device__ __forceinline__ void cp16(uint32_t dst, const void* src) {
    asm volatile("cp.async.cg.shared.global [%0], [%1], 16;" :: "r"(dst), "l"(src));
}
__device__ __forceinline__ void cp_commit() {
    asm volatile("cp.async.commit_group;" ::: "memory");
}
__device__ __forceinline__ void cp_wait1() {
    asm volatile("cp.async.wait_group 1;" ::: "memory");
}
__device__ __forceinline__ void ldsm_x4(uint32_t& r0, uint32_t& r1, uint32_t& r2,
                                        uint32_t& r3, uint32_t addr) {
    asm volatile("ldmatrix.sync.aligned.m8n8.x4.shared.b16 {%0,%1,%2,%3}, [%4];"
                 : "=r"(r0), "=r"(r1), "=r"(r2), "=r"(r3) : "r"(addr));
}
__device__ __forceinline__ void ldsm_x2(uint32_t& r0, uint32_t& r1, uint32_t addr) {
    asm volatile("ldmatrix.sync.aligned.m8n8.x2.shared.b16 {%0,%1}, [%2];"
                 : "=r"(r0), "=r"(r1) : "r"(addr));
}
__device__ __forceinline__ void mma_bf16(float& c0, float& c1, float& c2, float& c3,
                                         uint32_t a0, uint32_t a1, uint32_t a2, uint32_t a3,
                                         uint32_t b0, uint32_t b1) {
    asm volatile(
        "mma.sync.aligned.m16n8k16.row.col.f32.bf16.bf16.f32 "
        "{%0,%1,%2,%3}, {%4,%5,%6,%7}, {%8,%9}, {%0,%1,%2,%3};"
        : "+f"(c0), "+f"(c1), "+f"(c2), "+f"(c3)
        : "r"(a0), "r"(a1), "r"(a2), "r"(a3), "r"(b0), "r"(b1));
}

// ---------------------------------------------------------------------------
// K1: l2-normalize each token row of x -> g_xn AND bf16 split rows of g_A.
// ---------------------------------------------------------------------------
__global__ void k_normalize(const float* __restrict__ x) {
    int t = blockIdx.x;
    const float4* row = (const float4*)(x + (size_t)t * DIM);
    float4 a = row[threadIdx.x];                 // 128 threads * 4 = 512
    float ss = a.x * a.x + a.y * a.y + a.z * a.z + a.w * a.w;
    #pragma unroll
    for (int o = 16; o > 0; o >>= 1) ss += __shfl_xor_sync(0xffffffffu, ss, o);
    __shared__ float warpsum[4];
    __shared__ float s_inv;
    if ((threadIdx.x & 31) == 0) warpsum[threadIdx.x >> 5] = ss;
    __syncthreads();
    if (threadIdx.x == 0) {
        float tot = warpsum[0] + warpsum[1] + warpsum[2] + warpsum[3];
        s_inv = 1.0f / fmaxf(sqrtf(tot), 1e-6f);
    }
    __syncthreads();
    float inv = s_inv;
    float v[4] = {a.x * inv, a.y * inv, a.z * inv, a.w * inv};
    ((float4*)(g_xn + (size_t)t * DIM))[threadIdx.x] = make_float4(v[0], v[1], v[2], v[3]);

    __nv_bfloat16 hi[4], lo[4];
    #pragma unroll
    for (int i = 0; i < 4; i++) {
        hi[i] = __float2bfloat16(v[i]);
        lo[i] = __float2bfloat16(v[i] - __bfloat162float(hi[i]));
    }
    __nv_bfloat16* rA = g_A + (size_t)t * KPRIME;
    int c = threadIdx.x * 4;
    *(__nv_bfloat162*)(rA + c)              = __nv_bfloat162(hi[0], hi[1]);
    *(__nv_bfloat162*)(rA + c + 2)          = __nv_bfloat162(hi[2], hi[3]);
    *(__nv_bfloat162*)(rA + 512 + c)        = __nv_bfloat162(hi[0], hi[1]);
    *(__nv_bfloat162*)(rA + 512 + c + 2)    = __nv_bfloat162(hi[2], hi[3]);
    *(__nv_bfloat162*)(rA + 1024 + c)       = __nv_bfloat162(lo[0], lo[1]);
    *(__nv_bfloat162*)(rA + 1024 + c + 2)   = __nv_bfloat162(lo[2], lo[3]);
}

// ---------------------------------------------------------------------------
// K1b: split embed into g_B = [hi | lo | hi]
// ---------------------------------------------------------------------------
__global__ void k_prep_b(const float* __restrict__ embed) {
    int c = blockIdx.x;
    float4 a = ((const float4*)(embed + (size_t)c * DIM))[threadIdx.x];
    float v[4] = {a.x, a.y, a.z, a.w};
    __nv_bfloat16 hi[4], lo[4];
    #pragma unroll
    for (int i = 0; i < 4; i++) {
        hi[i] = __float2bfloat16(v[i]);
        lo[i] = __float2bfloat16(v[i] - __bfloat162float(hi[i]));
    }
    __nv_bfloat16* rB = g_B + (size_t)c * KPRIME;
    int d = threadIdx.x * 4;
    *(__nv_bfloat162*)(rB + d)              = __nv_bfloat162(hi[0], hi[1]);
    *(__nv_bfloat162*)(rB + d + 2)          = __nv_bfloat162(hi[2], hi[3]);
    *(__nv_bfloat162*)(rB + 512 + d)        = __nv_bfloat162(lo[0], lo[1]);
    *(__nv_bfloat162*)(rB + 512 + d + 2)    = __nv_bfloat162(lo[2], lo[3]);
    *(__nv_bfloat162*)(rB + 1024 + d)       = __nv_bfloat162(hi[0], hi[1]);
    *(__nv_bfloat162*)(rB + 1024 + d + 2)   = __nv_bfloat162(hi[2], hi[3]);
}

// ---------------------------------------------------------------------------
// K2: dist = g_A @ g_B^T via mma.sync bf16 (HMMA), K'=1536.
// 128x128 tile, BK=32, 3-stage cp.async ring, 8 warps (2 M x 4 N), warp 64x32.
// ---------------------------------------------------------------------------
#define BK       32
#define NITERS   (KPRIME / BK)        // 48
#define NSTAGES  3
#define ASTRIDE  40                    // bf16 elems per smem row (32 + 8 pad)
#define ATILE_B  (128 * ASTRIDE * 2)   // 10240 bytes
#define STAGE_B  (2 * ATILE_B)         // 20480 bytes (A + B)
#define SMEM_TOT (NSTAGES * STAGE_B)   // 61440 bytes

extern __shared__ char dyn_smem[];

__device__ __forceinline__ void load_tile(uint32_t sbase, int stage, int iter,
                                          int tid, int rowBase, int colBase) {
    int k0 = iter * BK;
    uint32_t st = sbase + stage * STAGE_B;
    #pragma unroll
    for (int i = 0; i < 4; i++) {
        int q = i * 256 + tid;            // 0..1023
        int isA = q < 512;
        int qq = isA ? q : q - 512;
        int row = qq >> 2;
        int seg = qq & 3;                 // 8 bf16 (16B) per seg
        const __nv_bfloat16* src =
            (isA ? g_A + (size_t)(rowBase + row) * KPRIME
                 : g_B + (size_t)(colBase + row) * KPRIME) + k0 + seg * 8;
        uint32_t dst = st + (isA ? 0 : ATILE_B) + (row * ASTRIDE + seg * 8) * 2;
        cp16(dst, src);
    }
}

__global__ void __launch_bounds__(256)
k_gemm_mma(float* __restrict__ dist) {
    uint32_t sbase = smem_u32(dyn_smem);
    int tid  = threadIdx.x;
    int wid  = tid >> 5;
    int lane = tid & 31;
    int warpM = wid >> 2;      // 0..1  (64 rows each)
    int warpN = wid & 3;       // 0..3  (32 cols each)
    int rowBase = blockIdx.y * 128;
    int colBase = blockIdx.x * 128;

    float acc[4][4][4];
    #pragma unroll
    for (int mi = 0; mi < 4; mi++)
        #pragma unroll
        for (int ni = 0; ni < 4; ni++)
            #pragma unroll
            for (int r = 0; r < 4; r++) acc[mi][ni][r] = 0.0f;

    // ldmatrix source addresses (fixed per thread, offset by stage/kstep)
    int amat = lane >> 3, ar = lane & 7;
    int arow_in = (amat & 1) * 8 + ar;
    int ak_in   = (amat >> 1) * 8;
    int ml = lane & 15;
    int brow_in = ml & 7;
    int bk_in   = (ml >> 3) * 8;

    // Prologue: stages 0,1
    load_tile(sbase, 0, 0, tid, rowBase, colBase);
    cp_commit();
    load_tile(sbase, 1, 1, tid, rowBase, colBase);
    cp_commit();

    for (int it = 0; it < NITERS; it++) {
        int stage = it % NSTAGES;
        cp_wait1();
        __syncthreads();
        // prefetch iter it+2
        if (it + 2 < NITERS)
            load_tile(sbase, (it + 2) % NSTAGES, it + 2, tid, rowBase, colBase);
        cp_commit();

        uint32_t sA = sbase + stage * STAGE_B;
        uint32_t sB = sA + ATILE_B;
        #pragma unroll
        for (int ks = 0; ks < 2; ks++) {
            uint32_t a0[4], a1[4], a2[4], a3[4];
            #pragma unroll
            for (int mi = 0; mi < 4; mi++) {
                uint32_t addr = sA +
                    ((warpM * 64 + mi * 16 + arow_in) * ASTRIDE + ks * 16 + ak_in) * 2;
                ldsm_x4(a0[mi], a1[mi], a2[mi], a3[mi], addr);
            }
            uint32_t b0[4], b1[4];
            #pragma unroll
            for (int ni = 0; ni < 4; ni++) {
                uint32_t addr = sB +
                    ((warpN * 32 + ni * 8 + brow_in) * ASTRIDE + ks * 16 + bk_in) * 2;
                ldsm_x2(b0[ni], b1[ni], addr);
            }
            #pragma unroll
            for (int mi = 0; mi < 4; mi++)
                #pragma unroll
                for (int ni = 0; ni < 4; ni++)
                    mma_bf16(acc[mi][ni][0], acc[mi][ni][1], acc[mi][ni][2], acc[mi][ni][3],
                             a0[mi], a1[mi], a2[mi], a3[mi], b0[ni], b1[ni]);
        }
    }

    // Epilogue: thread t holds rows g=(t%32)/4 (+8), cols (t%4)*2 per (mi,ni)
    int g = lane >> 2;
    int cq = (lane & 3) * 2;
    #pragma unroll
    for (int mi = 0; mi < 4; mi++) {
        int r0 = rowBase + warpM * 64 + mi * 16 + g;
        #pragma unroll
        for (int ni = 0; ni < 4; ni++) {
            int cc = colBase + warpN * 32 + ni * 8 + cq;
            *(float2*)(dist + (size_t)r0 * CODES + cc) =
                make_float2(acc[mi][ni][0], acc[mi][ni][1]);
            *(float2*)(dist + (size_t)(r0 + 8) * CODES + cc) =
                make_float2(acc[mi][ni][2], acc[mi][ni][3]);
        }
    }
}

// ---------------------------------------------------------------------------
// K3: row argmax of dist (first-max tie break).
// ---------------------------------------------------------------------------
__global__ void k_argmax(const float* __restrict__ dist, float* __restrict__ out_ind) {
    int t = blockIdx.x;
    const float4* row = (const float4*)(dist + (size_t)t * CODES);
    float best = -INFINITY;
    int bi = 0;
    for (int c4 = threadIdx.x; c4 < CODES / 4; c4 += 256) {
        float4 v = row[c4];
        int c = c4 * 4;
        if (v.x > best) { best = v.x; bi = c; }
        if (v.y > best) { best = v.y; bi = c + 1; }
        if (v.z > best) { best = v.z; bi = c + 2; }
        if (v.w > best) { best = v.w; bi = c + 3; }
    }
    __shared__ float sv[256];
    __shared__ int   si[256];
    sv[threadIdx.x] = best;
    si[threadIdx.x] = bi;
    __syncthreads();
    for (int s = 128; s > 0; s >>= 1) {
        if (threadIdx.x < s) {
            float ov = sv[threadIdx.x + s];
            int   oi = si[threadIdx.x + s];
            if (ov > sv[threadIdx.x] ||
                (ov == sv[threadIdx.x] && oi < si[threadIdx.x])) {
                sv[threadIdx.x] = ov;
                si[threadIdx.x] = oi;
            }
        }
        __syncthreads();
    }
    if (threadIdx.x == 0) {
        g_ind[t] = si[0];
        out_ind[t] = (float)si[0];
    }
}

// ---------------------------------------------------------------------------
// K4: quantize = embed[ind]
// ---------------------------------------------------------------------------
__global__ void k_quantize(const float* __restrict__ embed, float* __restrict__ out_q) {
    int t = blockIdx.x;
    int c = g_ind[t];
    float4 v = ((const float4*)(embed + (size_t)c * DIM))[threadIdx.x];
    ((float4*)(out_q + (size_t)t * DIM))[threadIdx.x] = v;
}

// ---------------------------------------------------------------------------
// K5a: init EMA outputs with DECAY * old
// ---------------------------------------------------------------------------
__global__ void k_init_ema(const float* __restrict__ cs, const float* __restrict__ ea,
                           float* __restrict__ out_cs, float* __restrict__ out_ea) {
    size_t total = (size_t)CODES * DIM;
    for (size_t i = blockIdx.x * (size_t)blockDim.x + threadIdx.x; i < total;
         i += (size_t)gridDim.x * blockDim.x) {
        out_ea[i] = DECAYF * ea[i];
        if (i < CODES) out_cs[i] = DECAYF * cs[i];
    }
}

// ---------------------------------------------------------------------------
// K5b: scatter (1-DECAY)*xn into embed_avg[ind], (1-DECAY) into cluster_size[ind]
// ---------------------------------------------------------------------------
__global__ void k_scatter(float* __restrict__ out_cs, float* __restrict__ out_ea) {
    int t = blockIdx.x;
    int c = g_ind[t];
    const float4* xr = (const float4*)(g_xn + (size_t)t * DIM);
    float* er = out_ea + (size_t)c * DIM;
    float4 v = xr[threadIdx.x];
    int d = threadIdx.x * 4;
    atomicAdd(er + d + 0, OMDF * v.x);
    atomicAdd(er + d + 1, OMDF * v.y);
    atomicAdd(er + d + 2, OMDF * v.z);
    atomicAdd(er + d + 3, OMDF * v.w);
    if (threadIdx.x == 0) atomicAdd(out_cs + c, OMDF);
}

// ---------------------------------------------------------------------------
// K6: denom = sum(new_cluster_size)
// ---------------------------------------------------------------------------
__global__ void k_denom(const float* __restrict__ out_cs) {
    float s = 0.0f;
    for (int i = threadIdx.x; i < CODES; i += 1024) s += out_cs[i];
    #pragma unroll
    for (int o = 16; o > 0; o >>= 1) s += __shfl_xor_sync(0xffffffffu, s, o);
    __shared__ float ws[32];
    if ((threadIdx.x & 31) == 0) ws[threadIdx.x >> 5] = s;
    __syncthreads();
    if (threadIdx.x == 0) {
        float tot = 0.0f;
        for (int i = 0; i < 32; i++) tot += ws[i];
        g_denom = tot;
    }
}

// ---------------------------------------------------------------------------
// K7: new_embed = l2norm(new_embed_avg / smoothed)
// ---------------------------------------------------------------------------
__global__ void k_newembed(const float* __restrict__ out_cs,
                           const float* __restrict__ out_ea,
                           float* __restrict__ out_e) {
    int c = blockIdx.x;
    float denom = g_denom;
    float smoothed = (out_cs[c] + EPSF) / (denom + (float)CODES * EPSF) * denom;
    float invs = 1.0f / smoothed;
    float4 v = ((const float4*)(out_ea + (size_t)c * DIM))[threadIdx.x];
    float4 w = make_float4(v.x * invs, v.y * invs, v.z * invs, v.w * invs);
    float ss = w.x * w.x + w.y * w.y + w.z * w.z + w.w * w.w;
    #pragma unroll
    for (int o = 16; o > 0; o >>= 1) ss += __shfl_xor_sync(0xffffffffu, ss, o);
    __shared__ float warpsum[4];
    __shared__ float s_inv;
    if ((threadIdx.x & 31) == 0) warpsum[threadIdx.x >> 5] = ss;
    __syncthreads();
    if (threadIdx.x == 0) {
        float tot = warpsum[0] + warpsum[1] + warpsum[2] + warpsum[3];
        s_inv = 1.0f / fmaxf(sqrtf(tot), 1e-6f);
    }
    __syncthreads();
    float inv = s_inv;
    float4 o4 = make_float4(w.x * inv, w.y * inv, w.z * inv, w.w * inv);
    ((float4*)(out_e + (size_t)c * DIM))[threadIdx.x] = o4;
}

// ---------------------------------------------------------------------------
extern "C" void kernel_launch(void* const* d_in, const int* in_sizes, int n_in,
                              void* d_out, int out_size) {
    const float* x     = (const float*)d_in[0];
    const float* embed = (const float*)d_in[1];
    const float* cs    = (const float*)d_in[2];
    const float* ea    = (const float*)d_in[3];
    float* out = (float*)d_out;

    cudaFuncSetAttribute(k_gemm_mma, cudaFuncAttributeMaxDynamicSharedMemorySize,
                         SMEM_TOT);

    k_normalize<<<TOKENS, 128>>>(x);
    k_prep_b<<<CODES, 128>>>(embed);
    k_gemm_mma<<<dim3(CODES / 128, TOKENS / 128), 256, SMEM_TOT>>>(out + OFF_DIST);
    k_argmax<<<TOKENS, 256>>>(out + OFF_DIST, out + OFF_IND);
    k_quantize<<<TOKENS, 128>>>(embed, out + OFF_Q);
    k_init_ema<<<2048, 256>>>(cs, ea, out + OFF_CS, out + OFF_EA);
    k_scatter<<<TOKENS, 128>>>(out + OFF_CS, out + OFF_EA);
    k_denom<<<1, 1024>>>(out + OFF_CS);
    k_newembed<<<CODES, 128>>>(out + OFF_CS, out + OFF_EA, out + OFF_E);
}

// round 6
// speedup vs baseline: 5.8061x; 2.8167x over previous
#include <cuda_runtime.h>
#include <cuda_fp16.h>
#include <cstdint>
#include <math.h>

// Problem constants
#define TOKENS 8192        // b*n = 4*2048
#define DIM    512
#define CODES  8192
#define DECAYF 0.8f
#define OMDF   (1.0f - 0.8f)
#define EPSF   1e-5f
#define MARGIN 3e-3f

// Output layout (floats), tuple order flattened
#define OFF_Q    ((size_t)0)
#define OFF_IND  ((size_t)4194304)
#define OFF_DIST ((size_t)4202496)
#define OFF_CS   ((size_t)71311360)
#define OFF_EA   ((size_t)71319552)
#define OFF_E    ((size_t)75513856)

// Scratch (device globals; no allocations allowed)
__device__ float g_xn[(size_t)TOKENS * DIM];   // l2-normalized x (fp32)
__device__ int   g_ind[TOKENS];
__device__ float g_denom;
__device__ __half g_A[(size_t)TOKENS * DIM];   // fp16(xn)
__device__ __half g_B[(size_t)CODES  * DIM];   // fp16(embed)
__device__ float g_tilemax[(size_t)TOKENS * 64];  // per (row, 128-col tile) max

// ---------------------------------------------------------------------------
// helpers
// ---------------------------------------------------------------------------
__device__ __forceinline__ uint32_t smem_u32(const void* p) {
    uint32_t a;
    asm("{ .reg .u64 t; cvta.to.shared.u64 t, %1; cvt.u32.u64 %0, t; }" : "=r"(a) : "l"(p));
    return a;
}
__device__ __forceinline__ void cp16(uint32_t dst, const void* src) {
    asm volatile("cp.async.cg.shared.global [%0], [%1], 16;" :: "r"(dst), "l"(src));
}
__device__ __forceinline__ void cp_commit() {
    asm volatile("cp.async.commit_group;" ::: "memory");
}
__device__ __forceinline__ void cp_wait1() {
    asm volatile("cp.async.wait_group 1;" ::: "memory");
}
__device__ __forceinline__ void ldsm_x4(uint32_t& r0, uint32_t& r1, uint32_t& r2,
                                        uint32_t& r3, uint32_t addr) {
    asm volatile("ldmatrix.sync.aligned.m8n8.x4.shared.b16 {%0,%1,%2,%3}, [%4];"
                 : "=r"(r0), "=r"(r1), "=r"(r2), "=r"(r3) : "r"(addr));
}
__device__ __forceinline__ void ldsm_x2(uint32_t& r0, uint32_t& r1, uint32_t addr) {
    asm volatile("ldmatrix.sync.aligned.m8n8.x2.shared.b16 {%0,%1}, [%2];"
                 : "=r"(r0), "=r"(r1) : "r"(addr));
}
__device__ __forceinline__ void mma_fp16(float& c0, float& c1, float& c2, float& c3,
                                         uint32_t a0, uint32_t a1, uint32_t a2, uint32_t a3,
                                         uint32_t b0, uint32_t b1) {
    asm volatile(
        "mma.sync.aligned.m16n8k16.row.col.f32.f16.f16.f32 "
        "{%0,%1,%2,%3}, {%4,%5,%6,%7}, {%8,%9}, {%0,%1,%2,%3};"
        : "+f"(c0), "+f"(c1), "+f"(c2), "+f"(c3)
        : "r"(a0), "r"(a1), "r"(a2), "r"(a3), "r"(b0), "r"(b1));
}

// ---------------------------------------------------------------------------
// K1: l2-normalize each token row of x -> g_xn (fp32) + g_A (fp16).
// ---------------------------------------------------------------------------
__global__ void k_normalize(const float* __restrict__ x) {
    int t = blockIdx.x;
    const float4* row = (const float4*)(x + (size_t)t * DIM);
    float4 a = row[threadIdx.x];                 // 128 threads * 4 = 512
    float ss = a.x * a.x + a.y * a.y + a.z * a.z + a.w * a.w;
    #pragma unroll
    for (int o = 16; o > 0; o >>= 1) ss += __shfl_xor_sync(0xffffffffu, ss, o);
    __shared__ float warpsum[4];
    __shared__ float s_inv;
    if ((threadIdx.x & 31) == 0) warpsum[threadIdx.x >> 5] = ss;
    __syncthreads();
    if (threadIdx.x == 0) {
        float tot = warpsum[0] + warpsum[1] + warpsum[2] + warpsum[3];
        s_inv = 1.0f / fmaxf(sqrtf(tot), 1e-6f);
    }
    __syncthreads();
    float inv = s_inv;
    float v[4] = {a.x * inv, a.y * inv, a.z * inv, a.w * inv};
    ((float4*)(g_xn + (size_t)t * DIM))[threadIdx.x] = make_float4(v[0], v[1], v[2], v[3]);
    __half* rA = g_A + (size_t)t * DIM;
    int c = threadIdx.x * 4;
    *(__half2*)(rA + c)     = __half2(__float2half_rn(v[0]), __float2half_rn(v[1]));
    *(__half2*)(rA + c + 2) = __half2(__float2half_rn(v[2]), __float2half_rn(v[3]));
}

// ---------------------------------------------------------------------------
// K1b: g_B = fp16(embed)
// ---------------------------------------------------------------------------
__global__ void k_prep_b(const float* __restrict__ embed) {
    int c = blockIdx.x;
    float4 a = ((const float4*)(embed + (size_t)c * DIM))[threadIdx.x];
    __half* rB = g_B + (size_t)c * DIM;
    int d = threadIdx.x * 4;
    *(__half2*)(rB + d)     = __half2(__float2half_rn(a.x), __float2half_rn(a.y));
    *(__half2*)(rB + d + 2) = __half2(__float2half_rn(a.z), __float2half_rn(a.w));
}

// ---------------------------------------------------------------------------
// K2: dist = g_A @ g_B^T via mma.sync fp16 (HMMA), K=512, plus per-tile row max.
// 128x128 tile, BK=32, 3-stage cp.async ring, 8 warps (2 M x 4 N), warp 64x32.
// ---------------------------------------------------------------------------
#define BK       32
#define NITERS   (DIM / BK)            // 16
#define NSTAGES  3
#define ASTRIDE  40                    // fp16 elems per smem row (32 + 8 pad)
#define ATILE_B  (128 * ASTRIDE * 2)   // 10240 bytes
#define STAGE_B  (2 * ATILE_B)         // 20480 bytes (A + B)
#define SMEM_TOT (NSTAGES * STAGE_B)   // 61440 bytes

extern __shared__ char dyn_smem[];

__device__ __forceinline__ void load_tile(uint32_t sbase, int stage, int iter,
                                          int tid, int rowBase, int colBase) {
    int k0 = iter * BK;
    uint32_t st = sbase + stage * STAGE_B;
    #pragma unroll
    for (int i = 0; i < 4; i++) {
        int q = i * 256 + tid;            // 0..1023
        int isA = q < 512;
        int qq = isA ? q : q - 512;
        int row = qq >> 2;
        int seg = qq & 3;                 // 8 fp16 (16B) per seg
        const __half* src =
            (isA ? g_A + (size_t)(rowBase + row) * DIM
                 : g_B + (size_t)(colBase + row) * DIM) + k0 + seg * 8;
        uint32_t dst = st + (isA ? 0 : ATILE_B) + (row * ASTRIDE + seg * 8) * 2;
        cp16(dst, src);
    }
}

__global__ void __launch_bounds__(256, 2)
k_gemm_mma(float* __restrict__ dist) {
    __shared__ float s_rm[128][4];
    uint32_t sbase = smem_u32(dyn_smem);
    int tid  = threadIdx.x;
    int wid  = tid >> 5;
    int lane = tid & 31;
    int warpM = wid >> 2;      // 0..1  (64 rows each)
    int warpN = wid & 3;       // 0..3  (32 cols each)
    int rowBase = blockIdx.y * 128;
    int colBase = blockIdx.x * 128;

    float acc[4][4][4];
    #pragma unroll
    for (int mi = 0; mi < 4; mi++)
        #pragma unroll
        for (int ni = 0; ni < 4; ni++)
            #pragma unroll
            for (int r = 0; r < 4; r++) acc[mi][ni][r] = 0.0f;

    int amat = lane >> 3, ar = lane & 7;
    int arow_in = (amat & 1) * 8 + ar;
    int ak_in   = (amat >> 1) * 8;
    int ml = lane & 15;
    int brow_in = ml & 7;
    int bk_in   = (ml >> 3) * 8;

    load_tile(sbase, 0, 0, tid, rowBase, colBase);
    cp_commit();
    load_tile(sbase, 1, 1, tid, rowBase, colBase);
    cp_commit();

    for (int it = 0; it < NITERS; it++) {
        int stage = it % NSTAGES;
        cp_wait1();
        __syncthreads();
        if (it + 2 < NITERS)
            load_tile(sbase, (it + 2) % NSTAGES, it + 2, tid, rowBase, colBase);
        cp_commit();

        uint32_t sA = sbase + stage * STAGE_B;
        uint32_t sB = sA + ATILE_B;
        #pragma unroll
        for (int ks = 0; ks < 2; ks++) {
            uint32_t a0[4], a1[4], a2[4], a3[4];
            #pragma unroll
            for (int mi = 0; mi < 4; mi++) {
                uint32_t addr = sA +
                    ((warpM * 64 + mi * 16 + arow_in) * ASTRIDE + ks * 16 + ak_in) * 2;
                ldsm_x4(a0[mi], a1[mi], a2[mi], a3[mi], addr);
            }
            uint32_t b0[4], b1[4];
            #pragma unroll
            for (int ni = 0; ni < 4; ni++) {
                uint32_t addr = sB +
                    ((warpN * 32 + ni * 8 + brow_in) * ASTRIDE + ks * 16 + bk_in) * 2;
                ldsm_x2(b0[ni], b1[ni], addr);
            }
            #pragma unroll
            for (int mi = 0; mi < 4; mi++)
                #pragma unroll
                for (int ni = 0; ni < 4; ni++)
                    mma_fp16(acc[mi][ni][0], acc[mi][ni][1], acc[mi][ni][2], acc[mi][ni][3],
                             a0[mi], a1[mi], a2[mi], a3[mi], b0[ni], b1[ni]);
        }
    }

    // Epilogue: write dist + per-warp row maxes
    int g = lane >> 2;
    int cq = (lane & 3) * 2;
    #pragma unroll
    for (int mi = 0; mi < 4; mi++) {
        int r0 = rowBase + warpM * 64 + mi * 16 + g;
        float mlo = -INFINITY, mhi = -INFINITY;
        #pragma unroll
        for (int ni = 0; ni < 4; ni++) {
            int cc = colBase + warpN * 32 + ni * 8 + cq;
            *(float2*)(dist + (size_t)r0 * CODES + cc) =
                make_float2(acc[mi][ni][0], acc[mi][ni][1]);
            *(float2*)(dist + (size_t)(r0 + 8) * CODES + cc) =
                make_float2(acc[mi][ni][2], acc[mi][ni][3]);
            mlo = fmaxf(mlo, fmaxf(acc[mi][ni][0], acc[mi][ni][1]));
            mhi = fmaxf(mhi, fmaxf(acc[mi][ni][2], acc[mi][ni][3]));
        }
        #pragma unroll
        for (int o = 1; o < 4; o <<= 1) {
            mlo = fmaxf(mlo, __shfl_xor_sync(0xffffffffu, mlo, o));
            mhi = fmaxf(mhi, __shfl_xor_sync(0xffffffffu, mhi, o));
        }
        if ((lane & 3) == 0) {
            s_rm[warpM * 64 + mi * 16 + g][warpN]     = mlo;
            s_rm[warpM * 64 + mi * 16 + g + 8][warpN] = mhi;
        }
    }
    __syncthreads();
    if (tid < 128) {
        float m = fmaxf(fmaxf(s_rm[tid][0], s_rm[tid][1]),
                        fmaxf(s_rm[tid][2], s_rm[tid][3]));
        g_tilemax[(size_t)(rowBase + tid) * 64 + blockIdx.x] = m;
    }
}

// ---------------------------------------------------------------------------
// K3: per-row candidate refinement + exact fp32 argmax + quantize gather.
// One block (128 threads) per token row.
// ---------------------------------------------------------------------------
__global__ void __launch_bounds__(128)
k_select(const float* __restrict__ dist, const float* __restrict__ embed,
         float* __restrict__ out_ind, float* __restrict__ out_q) {
    int t = blockIdx.x;
    int tid = threadIdx.x;
    int wid = tid >> 5, lane = tid & 31;

    __shared__ float s_tm[64];
    __shared__ float s_M;
    __shared__ int   s_cand[64];
    __shared__ int   s_ncand;
    __shared__ float s_red[4];
    __shared__ int   s_best;

    if (tid < 64) s_tm[tid] = g_tilemax[(size_t)t * 64 + tid];
    if (tid == 0) s_ncand = 0;
    __syncthreads();
    if (tid < 32) {
        float m = fmaxf(s_tm[tid], s_tm[tid + 32]);
        #pragma unroll
        for (int o = 16; o > 0; o >>= 1) m = fmaxf(m, __shfl_xor_sync(0xffffffffu, m, o));
        if (tid == 0) s_M = m;
    }
    __syncthreads();
    float thr = s_M - MARGIN;
    const float* drow = dist + (size_t)t * CODES;
    for (int tile = 0; tile < 64; tile++) {
        if (s_tm[tile] > thr) {
            float v = drow[tile * 128 + tid];
            if (v > thr) {
                int p = atomicAdd(&s_ncand, 1);
                if (p < 64) s_cand[p] = tile * 128 + tid;
            }
        }
    }
    __syncthreads();
    int nc = min(s_ncand, 64);

    float4 xv = ((const float4*)(g_xn + (size_t)t * DIM))[tid];
    float bestv = -INFINITY;
    int   besti = CODES;
    for (int ci = 0; ci < nc; ci++) {
        int c = s_cand[ci];
        float4 ev = ((const float4*)(embed + (size_t)c * DIM))[tid];
        float p = xv.x * ev.x + xv.y * ev.y + xv.z * ev.z + xv.w * ev.w;
        #pragma unroll
        for (int o = 16; o > 0; o >>= 1) p += __shfl_xor_sync(0xffffffffu, p, o);
        if (lane == 0) s_red[wid] = p;
        __syncthreads();
        if (tid == 0) {
            float d = (s_red[0] + s_red[1]) + (s_red[2] + s_red[3]);
            if (d > bestv || (d == bestv && c < besti)) { bestv = d; besti = c; }
        }
        __syncthreads();
    }
    if (tid == 0) {
        g_ind[t] = besti;
        out_ind[t] = (float)besti;
        s_best = besti;
    }
    __syncthreads();
    float4 ev = ((const float4*)(embed + (size_t)s_best * DIM))[tid];
    ((float4*)(out_q + (size_t)t * DIM))[tid] = ev;
}

// ---------------------------------------------------------------------------
// K5a: init EMA outputs with DECAY * old
// ---------------------------------------------------------------------------
__global__ void k_init_ema(const float* __restrict__ cs, const float* __restrict__ ea,
                           float* __restrict__ out_cs, float* __restrict__ out_ea) {
    size_t total = (size_t)CODES * DIM;
    for (size_t i = blockIdx.x * (size_t)blockDim.x + threadIdx.x; i < total;
         i += (size_t)gridDim.x * blockDim.x) {
        out_ea[i] = DECAYF * ea[i];
        if (i < CODES) out_cs[i] = DECAYF * cs[i];
    }
}

// ---------------------------------------------------------------------------
// K5b: scatter (1-DECAY)*xn into embed_avg[ind], (1-DECAY) into cluster_size[ind]
// ---------------------------------------------------------------------------
__global__ void k_scatter(float* __restrict__ out_cs, float* __restrict__ out_ea) {
    int t = blockIdx.x;
    int c = g_ind[t];
    const float4* xr = (const float4*)(g_xn + (size_t)t * DIM);
    float* er = out_ea + (size_t)c * DIM;
    float4 v = xr[threadIdx.x];
    int d = threadIdx.x * 4;
    atomicAdd(er + d + 0, OMDF * v.x);
    atomicAdd(er + d + 1, OMDF * v.y);
    atomicAdd(er + d + 2, OMDF * v.z);
    atomicAdd(er + d + 3, OMDF * v.w);
    if (threadIdx.x == 0) atomicAdd(out_cs + c, OMDF);
}

// ---------------------------------------------------------------------------
// K6: denom = sum(new_cluster_size)
// ---------------------------------------------------------------------------
__global__ void k_denom(const float* __restrict__ out_cs) {
    float s = 0.0f;
    for (int i = threadIdx.x; i < CODES; i += 1024) s += out_cs[i];
    #pragma unroll
    for (int o = 16; o > 0; o >>= 1) s += __shfl_xor_sync(0xffffffffu, s, o);
    __shared__ float ws[32];
    if ((threadIdx.x & 31) == 0) ws[threadIdx.x >> 5] = s;
    __syncthreads();
    if (threadIdx.x == 0) {
        float tot = 0.0f;
        for (int i = 0; i < 32; i++) tot += ws[i];
        g_denom = tot;
    }
}

// ---------------------------------------------------------------------------
// K7: new_embed = l2norm(new_embed_avg / smoothed)
// ---------------------------------------------------------------------------
__global__ void k_newembed(const float* __restrict__ out_cs,
                           const float* __restrict__ out_ea,
                           float* __restrict__ out_e) {
    int c = blockIdx.x;
    float denom = g_denom;
    float smoothed = (out_cs[c] + EPSF) / (denom + (float)CODES * EPSF) * denom;
    float invs = 1.0f / smoothed;
    float4 v = ((const float4*)(out_ea + (size_t)c * DIM))[threadIdx.x];
    float4 w = make_float4(v.x * invs, v.y * invs, v.z * invs, v.w * invs);
    float ss = w.x * w.x + w.y * w.y + w.z * w.z + w.w * w.w;
    #pragma unroll
    for (int o = 16; o > 0; o >>= 1) ss += __shfl_xor_sync(0xffffffffu, ss, o);
    __shared__ float warpsum[4];
    __shared__ float s_inv;
    if ((threadIdx.x & 31) == 0) warpsum[threadIdx.x >> 5] = ss;
    __syncthreads();
    if (threadIdx.x == 0) {
        float tot = warpsum[0] + warpsum[1] + warpsum[2] + warpsum[3];
        s_inv = 1.0f / fmaxf(sqrtf(tot), 1e-6f);
    }
    __syncthreads();
    float inv = s_inv;
    float4 o4 = make_float4(w.x * inv, w.y * inv, w.z * inv, w.w * inv);
    ((float4*)(out_e + (size_t)c * DIM))[threadIdx.x] = o4;
}

// ---------------------------------------------------------------------------
extern "C" void kernel_launch(void* const* d_in, const int* in_sizes, int n_in,
                              void* d_out, int out_size) {
    const float* x     = (const float*)d_in[0];
    const float* embed = (const float*)d_in[1];
    const float* cs    = (const float*)d_in[2];
    const float* ea    = (const float*)d_in[3];
    float* out = (float*)d_out;

    cudaFuncSetAttribute(k_gemm_mma, cudaFuncAttributeMaxDynamicSharedMemorySize,
                         SMEM_TOT);

    k_normalize<<<TOKENS, 128>>>(x);
    k_prep_b<<<CODES, 128>>>(embed);
    k_gemm_mma<<<dim3(CODES / 128, TOKENS / 128), 256, SMEM_TOT>>>(out + OFF_DIST);
    k_select<<<TOKENS, 128>>>(out + OFF_DIST, embed, out + OFF_IND, out + OFF_Q);
    k_init_ema<<<2048, 256>>>(cs, ea, out + OFF_CS, out + OFF_EA);
    k_scatter<<<TOKENS, 128>>>(out + OFF_CS, out + OFF_EA);
    k_denom<<<1, 1024>>>(out + OFF_CS);
    k_newembed<<<CODES, 128>>>(out + OFF_CS, out + OFF_EA, out + OFF_E);
}